// round 15
// baseline (speedup 1.0000x reference)
#include <cuda_runtime.h>
#include <math.h>

#define B 32
#define N 2048
#define BN (B*N)

// binning
#define G 32
#define GG (G*G)
#define ORG  (-4.5f)
#define WBIN (9.0f / (float)G)
#define INVW ((float)G / 9.0f)

#define ATHREADS 256
#define QC 8                      // query chunks per (dir,b): 1 query/thread
#define STHREADS 256
#define SBLOCKS (QC*B*2)          // 512 search blocks

// ---------------- scratch (device globals; zero at module load) -------------
__device__ float2 g_Pb[BN], g_Tb[BN];        // binned visible points (CSR data)
__device__ int    g_offP[B*1025], g_offT[B*1025];  // CSR offsets + total at [1024]
__device__ float  g_ppart[B*3];              // {point,mask,struct} per batch
__device__ float  g_chpart[2*B*QC];          // per (dir,b,qc) sqrt-sums
__device__ int    g_fticket;                 // combine ticket (winner resets)

__device__ __forceinline__ int binc(float x) {
    int i = (int)floorf((x - ORG) * INVW);
    return min(max(i, 0), G - 1);
}

// exclusive scan of 1024 smem counters; writes offsets in place + to global[0..1024]
__device__ __forceinline__ void scan1024(unsigned* arr, unsigned* wsum, int* gout, int tid) {
    __syncthreads();
    int lane = tid & 31, wid = tid >> 5;
    unsigned v0 = arr[tid*4+0], v1 = arr[tid*4+1], v2 = arr[tid*4+2], v3 = arr[tid*4+3];
    unsigned tsum = v0 + v1 + v2 + v3;
    unsigned pre = tsum;
    #pragma unroll
    for (int o = 1; o < 32; o <<= 1) {
        unsigned nv = __shfl_up_sync(0xffffffffu, pre, o);
        if (lane >= o) pre += nv;
    }
    if (lane == 31) wsum[wid] = pre;
    unsigned texcl = pre - tsum;
    __syncthreads();
    if (tid == 0) {
        unsigned acc = 0;
        for (int w = 0; w < 8; w++) { unsigned x = wsum[w]; wsum[w] = acc; acc += x; }
        wsum[8] = acc;
    }
    __syncthreads();
    unsigned off = wsum[wid] + texcl;
    arr[tid*4+0] = off;      gout[tid*4+0] = (int)off;      off += v0;
    arr[tid*4+1] = off;      gout[tid*4+1] = (int)off;      off += v1;
    arr[tid*4+2] = off;      gout[tid*4+2] = (int)off;      off += v2;
    arr[tid*4+3] = off;      gout[tid*4+3] = (int)off;
    if (tid == 0) gout[1024] = (int)wsum[8];
    __syncthreads();
}

// ---------------- kernel A: per-role bin count + scan + scatter (+ losses) ---
__global__ void __launch_bounds__(ATHREADS) sk_bin_kernel(
        const float* __restrict__ pred,
        const float* __restrict__ target,
        const float* __restrict__ smask) {
    int b = blockIdx.x, role = blockIdx.y, tid = threadIdx.x;  // role 0=P, 1=T
    __shared__ unsigned s_cnt[GG];     // 4 KB
    __shared__ unsigned s_wsum[9];
    __shared__ float red[24];          // 8 warps x 3

    for (int i = tid; i < GG; i += ATHREADS) s_cnt[i] = 0;
    __syncthreads();

    const float* base = role ? target : pred;
    float s_point = 0.f, s_mask = 0.f, s_struct = 0.f;

    #pragma unroll
    for (int it = 0; it < N/ATHREADS; it++) {
        int n = it * ATHREADS + tid;
        int idx = b * N + n;
        float c0 = base[idx*3+0], c1 = base[idx*3+1], c2 = base[idx*3+2];
        bool vis = (c2 == 1.0f);
        if (vis) atomicAdd(&s_cnt[binc(c1)*G + binc(c0)], 1u);
        if (role && vis) {
            float p0 = pred[idx*3+0], p1 = pred[idx*3+1];
            float d0 = p0 - c0, d1 = p1 - c1;
            s_point += d0*d0 + d1*d1;
            float m0 = smask[idx*2+0], m1 = smask[idx*2+1];
            float sm = fminf(fmaxf(m0 + m1, 0.f), 1.f);
            s_mask += sm;
            float e0 = d0*sm, e1 = d1*sm;
            s_struct += e0*e0 + e1*e1;
        }
    }

    int* gout = (role ? g_offT : g_offP) + b*1025;
    scan1024(s_cnt, s_wsum, gout, tid);

    float2* gpts = (role ? g_Tb : g_Pb) + b*N;
    #pragma unroll
    for (int it = 0; it < N/ATHREADS; it++) {
        int n = it * ATHREADS + tid;
        int idx = b * N + n;
        float c0 = base[idx*3+0], c1 = base[idx*3+1], c2 = base[idx*3+2];
        if (c2 == 1.0f) {
            unsigned slot = atomicAdd(&s_cnt[binc(c1)*G + binc(c0)], 1u);
            gpts[slot] = make_float2(c0, c1);
        }
    }

    if (role) {
        #pragma unroll
        for (int o = 16; o; o >>= 1) {
            s_point  += __shfl_xor_sync(0xffffffffu, s_point,  o);
            s_mask   += __shfl_xor_sync(0xffffffffu, s_mask,   o);
            s_struct += __shfl_xor_sync(0xffffffffu, s_struct, o);
        }
        int lane = tid & 31, wid = tid >> 5;
        if (lane == 0) { red[wid] = s_point; red[8+wid] = s_mask; red[16+wid] = s_struct; }
        __syncthreads();
        if (tid == 0) {
            float a = 0.f, c = 0.f, d = 0.f;
            for (int w = 0; w < 8; w++) { a += red[w]; c += red[8+w]; d += red[16+w]; }
            g_ppart[b*3+0] = a; g_ppart[b*3+1] = c; g_ppart[b*3+2] = d;
        }
    }
}

// ---------------- kernel B: warp-uniform smem search + fused combine ---------
__global__ void __launch_bounds__(STHREADS) sk_search_kernel(float* __restrict__ out) {
    int qc = blockIdx.x, b = blockIdx.y, dir = blockIdx.z;
    int db = dir * B + b;
    int tid = threadIdx.x;

    const float2 *Qp, *Dp;
    const int *Qoff, *Doff;
    if (dir == 0) { Qp = g_Pb + b*N; Qoff = g_offP + b*1025; Dp = g_Tb + b*N; Doff = g_offT + b*1025; }
    else          { Qp = g_Tb + b*N; Qoff = g_offT + b*1025; Dp = g_Pb + b*N; Doff = g_offP + b*1025; }

    // stage whole database + offsets in shared memory
    __shared__ float2 s_D[N];        // 16 KB
    __shared__ int    s_off[1025];   // 4.1 KB
    #pragma unroll
    for (int it = 0; it < N/STHREADS; it++)
        s_D[it*STHREADS + tid] = Dp[it*STHREADS + tid];
    #pragma unroll
    for (int it = 0; it < 1025/STHREADS + 1; it++) {
        int i = it*STHREADS + tid;
        if (i < 1025) s_off[i] = Doff[i];
    }
    int cntQ = Qoff[1024];
    __syncthreads();

    const unsigned FULL = 0xffffffffu;
    float sum = 0.f;
    int q = qc * STHREADS + tid;
    if (cntQ > 0) {
        bool valid = (q < cntQ);
        int q2 = min(q, cntQ - 1);
        float2 Qv = Qp[q2];
        int qbx = binc(Qv.x), qby = binc(Qv.y);
        float best = 3.0e38f;

        auto scan_span = [&](int s, int e) {
            for (int k = s; k < e; k++) {
                float2 p = s_D[k];
                float dx = Qv.x - p.x, dy = Qv.y - p.y;
                float d2 = fmaf(dx, dx, dy*dy);
                best = fminf(best, d2);
            }
        };

        // warp-union 3x3 window
        int I0 = max(__reduce_min_sync(FULL, qbx) - 1, 0);
        int I1 = min(__reduce_max_sync(FULL, qbx) + 1, G-1);
        int J0 = max(__reduce_min_sync(FULL, qby) - 1, 0);
        int J1 = min(__reduce_max_sync(FULL, qby) + 1, G-1);

        if (I1 - I0 <= 8) {
            // ---- warp-uniform path: all lanes scan identical spans ----------
            for (int j = J0; j <= J1; j++)
                scan_span(s_off[j*G + I0], s_off[j*G + I1 + 1]);

            // rect-ring expansion (rare): after rings <= rho, each lane's
            // covered Chebyshev radius is rho+1 (its +-1 box is inside rect)
            for (int c = 1; c < 2*G; c++) {
                float bd = (float)c * WBIN;
                if (!__any_sync(FULL, best > bd*bd)) break;
                int rho = c;
                int i0 = max(I0 - rho, 0), i1 = min(I1 + rho, G-1);
                int jt = J0 - rho, jb = J1 + rho;
                if (jt >= 0) scan_span(s_off[jt*G + i0], s_off[jt*G + i1 + 1]);
                if (jb < G)  scan_span(s_off[jb*G + i0], s_off[jb*G + i1 + 1]);
                int jj0 = max(J0 - rho + 1, 0), jj1 = min(J1 + rho - 1, G-1);
                if (I0 - rho >= 0) {
                    int ic = I0 - rho;
                    for (int j = jj0; j <= jj1; j++) scan_span(s_off[j*G + ic], s_off[j*G + ic + 1]);
                }
                if (I1 + rho < G) {
                    int ic = I1 + rho;
                    for (int j = jj0; j <= jj1; j++) scan_span(s_off[j*G + ic], s_off[j*G + ic + 1]);
                }
                if (i0 == 0 && i1 == G-1 && jt <= 0 && jb >= G-1) break;
            }
        } else {
            // ---- per-lane path (warp straddles a bin-row boundary) ----------
            {
                int i0 = max(qbx - 1, 0), i1 = min(qbx + 1, G-1);
                int j0 = max(qby - 1, 0), j1 = min(qby + 1, G-1);
                for (int j = j0; j <= j1; j++)
                    scan_span(s_off[j*G + i0], s_off[j*G + i1 + 1]);
            }
            for (int r = 2; r < G; r++) {
                float bd = (float)(r-1) * WBIN;
                if (best <= bd*bd) break;
                int i0 = max(qbx - r, 0), i1 = min(qbx + r, G-1);
                int jt = qby - r, jb = qby + r;
                if (jt >= 0) scan_span(s_off[jt*G + i0], s_off[jt*G + i1 + 1]);
                if (jb < G)  scan_span(s_off[jb*G + i0], s_off[jb*G + i1 + 1]);
                int jj0 = max(qby - r + 1, 0), jj1 = min(qby + r - 1, G-1);
                if (qbx - r >= 0) {
                    int ic = qbx - r;
                    for (int j = jj0; j <= jj1; j++) scan_span(s_off[j*G + ic], s_off[j*G + ic + 1]);
                }
                if (qbx + r < G) {
                    int ic = qbx + r;
                    for (int j = jj0; j <= jj1; j++) scan_span(s_off[j*G + ic], s_off[j*G + ic + 1]);
                }
            }
        }
        if (valid) sum = sqrtf(fmaxf(best, 1e-12f));
    }

    // block reduction of sqrt-sum
    __shared__ float wred[8];
    #pragma unroll
    for (int o = 16; o; o >>= 1) sum += __shfl_xor_sync(0xffffffffu, sum, o);
    if ((tid & 31) == 0) wred[tid >> 5] = sum;
    __syncthreads();

    __shared__ int s_ft;
    if (tid == 0) {
        float tot = 0.f;
        #pragma unroll
        for (int w = 0; w < 8; w++) tot += wred[w];
        g_chpart[db*QC + qc] = tot;
        __threadfence();
        s_ft = atomicAdd(&g_fticket, 1);
    }
    __syncthreads();
    if (s_ft != SBLOCKS - 1) return;
    if (tid == 0) g_fticket = 0;          // reset for next replay
    __threadfence();

    // ---- combine (winner block) ---------------------------------------------
    __shared__ float s_ch[2*B];
    volatile float* vcp = g_chpart;
    if (tid < 2*B) {
        float s = 0.f;
        #pragma unroll
        for (int c = 0; c < QC; c++) s += vcp[tid*QC + c];
        s_ch[tid] = s;
    }
    __syncthreads();

    float ch = 0.f, a = 0.f, c = 0.f, d = 0.f;
    if (tid < B) {
        float cp = (float)g_offP[tid*1025 + 1024];
        float ct = (float)g_offT[tid*1025 + 1024];
        float mp = s_ch[tid]     / fmaxf(cp, 1.f);   // dir0: queries = preds
        float mt = s_ch[B + tid] / fmaxf(ct, 1.f);   // dir1: queries = targets
        ch = (cp > 0.f && ct > 0.f) ? 0.5f * (mp + mt) : 0.f;
        a = g_ppart[tid*3+0]; c = g_ppart[tid*3+1]; d = g_ppart[tid*3+2];
    }
    if (tid < 32) {
        #pragma unroll
        for (int o = 16; o; o >>= 1) {
            ch += __shfl_xor_sync(0xffffffffu, ch, o);
            a  += __shfl_xor_sync(0xffffffffu, a,  o);
            c  += __shfl_xor_sync(0xffffffffu, c,  o);
            d  += __shfl_xor_sync(0xffffffffu, d,  o);
        }
        if (tid == 0) {
            float lc = ch / (float)B;
            float lp = a / (float)(B * N * 2);
            float ls = (c > 0.f) ? d / (float)(B * N * 2) : 0.f;
            out[0] = lp + 5.0f * lc + 2.0f * ls;
            out[1] = lp;
            out[2] = 0.f;
            out[3] = lc;
        }
    }
}

extern "C" void kernel_launch(void* const* d_in, const int* in_sizes, int n_in,
                              void* d_out, int out_size) {
    const float* pred   = (const float*)d_in[0];
    const float* target = (const float*)d_in[1];
    const float* smask  = (const float*)d_in[2];
    float* out = (float*)d_out;

    dim3 agrid(B, 2);
    sk_bin_kernel<<<agrid, ATHREADS>>>(pred, target, smask);
    dim3 sgrid(QC, B, 2);
    sk_search_kernel<<<sgrid, STHREADS>>>(out);
}